// round 15
// baseline (speedup 1.0000x reference)
#include <cuda_runtime.h>
#include <cstdint>
#include <cstddef>

#define HID 512
#define SEQ 2048
#define BATCH 64
#define VOCAB 32000

#define CHUNK 128
#define NCHUNK (SEQ / CHUNK)

// ---------------- scratch ----------------
__device__ float g_E[(size_t)VOCAB * HID];          // E' = embed @ W_ih0^T + biases
__device__ float g_ys[(size_t)SEQ * BATCH * HID];   // layer-0 outputs
__device__ float g_xb[(size_t)SEQ * BATCH * HID];   // layer-1 input term
__device__ float g_h1[(size_t)BATCH * HID];         // layer-1 h state across chunks

// ---------------- helpers ----------------
__device__ __forceinline__ unsigned smem_u32(const void* p) {
    unsigned r;
    asm("{ .reg .u64 t; cvta.to.shared.u64 t, %1; cvt.u32.u64 %0, t; }" : "=r"(r) : "l"(p));
    return r;
}
__device__ __forceinline__ unsigned ctarank() {
    unsigned r; asm("mov.u32 %0, %%cluster_ctarank;" : "=r"(r)); return r;
}
__device__ __forceinline__ void fma2(unsigned long long& d, unsigned long long a, unsigned long long b) {
    asm("fma.rn.f32x2 %0, %1, %2, %0;" : "+l"(d) : "l"(a), "l"(b));
}
__device__ __forceinline__ unsigned long long add2(unsigned long long a, unsigned long long b) {
    unsigned long long r;
    asm("add.rn.f32x2 %0, %1, %2;" : "=l"(r) : "l"(a), "l"(b));
    return r;
}
__device__ __forceinline__ unsigned long long pack2(float a) {
    unsigned long long r; asm("mov.b64 %0, {%1, %1};" : "=l"(r) : "f"(a)); return r;
}
__device__ __forceinline__ float lo2(unsigned long long a) { return __uint_as_float((unsigned)a); }
__device__ __forceinline__ float hi2(unsigned long long a) { return __uint_as_float((unsigned)(a >> 32)); }
__device__ __forceinline__ float2 unpack2(unsigned long long a) {
    return make_float2(lo2(a), hi2(a));
}
__device__ __forceinline__ void mbar_wait(unsigned mbar, unsigned parity) {
    unsigned done;
    asm volatile(
        "{\n\t.reg .pred p;\n\t"
        "mbarrier.try_wait.parity.acquire.cluster.shared::cta.b64 p, [%1], %2;\n\t"
        "selp.b32 %0, 1, 0, p;\n\t}"
        : "=r"(done) : "r"(mbar), "r"(parity) : "memory");
    if (!done) {
        asm volatile(
            "{\n\t.reg .pred P1;\n\t"
            "WL_%=:\n\t"
            "mbarrier.try_wait.parity.acquire.cluster.shared::cta.b64 P1, [%0], %1, 0x989680;\n\t"
            "@P1 bra.uni WD_%=;\n\t"
            "bra.uni WL_%=;\n\t"
            "WD_%=:\n\t}"
            :: "r"(mbar), "r"(parity) : "memory");
    }
}

// ---------------- GEMM: C[M][512] = A[M][512] @ W[512][512]^T + bi + bh ------
#define BM 128
#define BN 128
#define BK 16

__global__ void __launch_bounds__(256)
gemm_bias_kernel(const float* __restrict__ A, const float* __restrict__ W,
                 const float* __restrict__ bi, const float* __restrict__ bh,
                 float* __restrict__ C)
{
    __shared__ float As[BK][BM + 4];
    __shared__ float Bs[BK][BN + 4];

    int bm = blockIdx.x, bn = blockIdx.y;
    int tid = threadIdx.x;
    int tx = tid & 15, ty = tid >> 4;
    int ar = tid >> 2;
    int ac = (tid & 3) << 2;

    const float* Ap = A + (size_t)bm * BM * HID;
    const float* Wp = W + (size_t)bn * BN * HID;

    unsigned long long acc[8][4];
#pragma unroll
    for (int r = 0; r < 8; ++r)
#pragma unroll
        for (int c = 0; c < 4; ++c) acc[r][c] = 0ULL;

    for (int k0 = 0; k0 < HID; k0 += BK) {
        float4 a0 = *(const float4*)&Ap[(size_t)ar * HID + k0 + ac];
        float4 a1 = *(const float4*)&Ap[(size_t)(ar + 64) * HID + k0 + ac];
        float4 b0 = *(const float4*)&Wp[(size_t)ar * HID + k0 + ac];
        float4 b1 = *(const float4*)&Wp[(size_t)(ar + 64) * HID + k0 + ac];
        __syncthreads();
        As[ac + 0][ar] = a0.x; As[ac + 1][ar] = a0.y; As[ac + 2][ar] = a0.z; As[ac + 3][ar] = a0.w;
        As[ac + 0][ar + 64] = a1.x; As[ac + 1][ar + 64] = a1.y; As[ac + 2][ar + 64] = a1.z; As[ac + 3][ar + 64] = a1.w;
        Bs[ac + 0][ar] = b0.x; Bs[ac + 1][ar] = b0.y; Bs[ac + 2][ar] = b0.z; Bs[ac + 3][ar] = b0.w;
        Bs[ac + 0][ar + 64] = b1.x; Bs[ac + 1][ar + 64] = b1.y; Bs[ac + 2][ar + 64] = b1.z; Bs[ac + 3][ar + 64] = b1.w;
        __syncthreads();
#pragma unroll
        for (int k = 0; k < BK; ++k) {
            float4 av0 = *(const float4*)&As[k][ty * 4];
            float4 av1 = *(const float4*)&As[k][ty * 4 + 64];
            ulonglong2 bv0 = *(const ulonglong2*)&Bs[k][tx * 4];
            ulonglong2 bv1 = *(const ulonglong2*)&Bs[k][tx * 4 + 64];
            unsigned long long am[8];
            am[0] = pack2(av0.x); am[1] = pack2(av0.y); am[2] = pack2(av0.z); am[3] = pack2(av0.w);
            am[4] = pack2(av1.x); am[5] = pack2(av1.y); am[6] = pack2(av1.z); am[7] = pack2(av1.w);
#pragma unroll
            for (int r = 0; r < 8; ++r) {
                fma2(acc[r][0], am[r], bv0.x);
                fma2(acc[r][1], am[r], bv0.y);
                fma2(acc[r][2], am[r], bv1.x);
                fma2(acc[r][3], am[r], bv1.y);
            }
        }
    }

    int nb = bn * BN;
    float4 x0 = *(const float4*)&bi[nb + tx * 4];
    float4 y0 = *(const float4*)&bh[nb + tx * 4];
    float4 x1 = *(const float4*)&bi[nb + tx * 4 + 64];
    float4 y1 = *(const float4*)&bh[nb + tx * 4 + 64];
    float4 bias0 = make_float4(x0.x + y0.x, x0.y + y0.y, x0.z + y0.z, x0.w + y0.w);
    float4 bias1 = make_float4(x1.x + y1.x, x1.y + y1.y, x1.z + y1.z, x1.w + y1.w);
#pragma unroll
    for (int r = 0; r < 8; ++r) {
        int row_local = (r < 4) ? (ty * 4 + r) : (64 + ty * 4 + (r - 4));
        size_t row = (size_t)(bm * BM + row_local);
        float2 p0 = unpack2(acc[r][0]), p1 = unpack2(acc[r][1]);
        float2 p2 = unpack2(acc[r][2]), p3 = unpack2(acc[r][3]);
        float4 o0 = make_float4(p0.x + bias0.x, p0.y + bias0.y, p1.x + bias0.z, p1.y + bias0.w);
        float4 o1 = make_float4(p2.x + bias1.x, p2.y + bias1.y, p3.x + bias1.z, p3.y + bias1.w);
        *(float4*)&C[row * HID + nb + tx * 4] = o0;
        *(float4*)&C[row * HID + nb + tx * 4 + 64] = o1;
    }
}

// ---------------- recurrence chunk kernel (512 threads) ----------------
// 8 clusters x 8 CTAs. Cluster owns 8 batches; CTA r owns features
// [64r, 64r+64). Thread (jq=tid>>4 in 0..31, ks=tid&15): W_hh rows jbase+jq,
// jbase+jq+32, k-slice [32ks, 32ks+32) in 32 registers. 4 warps/SMSP for
// latency hiding (R14 was issue-starved at 2 warps/SMSP).
// h transposed in smem: [buf][kseg 16][k 32][batch 8], seg stride 260 floats.
// Per k: 2 LDS.128 (8 batches) feed 8 fma2. Butterfly reduce over 16 ks-lanes,
// lanes ks<8 (fs=ks&1, bp=ks>>1) apply tanh for 2 batches, stage float2; CTA
// pushes its 2KB slice to all 8 CTAs (2x st.shared::cluster.v4 / thread) +
// remote release-arrives on per-CTA mbarriers (count=8).
#define SEG 260
#define HBUFV (16 * SEG)
#define HBUF_BYTES (HBUFV * 4)

__global__ void __cluster_dims__(8, 1, 1) __launch_bounds__(512, 1)
rnn_chunk_kernel(const float* __restrict__ xterm,  // E' (L0) or g_xb (L1)
                 const int* __restrict__ src,      // tokens (L0) or nullptr
                 const float* __restrict__ Whh,    // [512][512]
                 float* __restrict__ ys,           // [S][B][512] (L0) or nullptr
                 float* __restrict__ outh,         // final hidden or nullptr
                 const float* __restrict__ hIn,    // h(t0-1) or nullptr
                 float* __restrict__ hOut,         // h(t0+CHUNK-1) or nullptr
                 int t0)
{
    __shared__ __align__(16) float sH[2 * HBUFV];
    __shared__ __align__(16) float4 sStage[128];   // 512 floats: [feat 64][batch 8]
    __shared__ __align__(8) unsigned long long sBarSto;

    const unsigned rank = ctarank();
    const int cid = blockIdx.x >> 3;
    const int gb0 = cid << 3;                 // 8 batches per cluster
    const int jbase = (int)rank << 6;
    const int tid = threadIdx.x;
    const int jq = tid >> 4;                  // 0..31
    const int ks = tid & 15;                  // 0..15 k segment (32 k each)
    const int f0 = jbase + jq;
    const int f1 = f0 + 32;

    float w0[32], w1[32];
#pragma unroll
    for (int i = 0; i < 32; ++i) {
        w0[i] = Whh[(size_t)f0 * HID + ks * 32 + i];
        w1[i] = Whh[(size_t)f1 * HID + ks * 32 + i];
    }

    // init h buffer for parity t0&1
    if (hIn) {
        for (int idx = tid; idx < 4096; idx += 512) {
            int bl = idx & 7, k = idx >> 3;
            sH[(t0 & 1) * HBUFV + (k >> 5) * SEG + (k & 31) * 8 + bl] =
                hIn[(size_t)(gb0 + bl) * HID + k];
        }
    } else {
        for (int i = tid; i < 2 * HBUFV; i += 512) sH[i] = 0.0f;
    }
    if (tid == 0)
        asm volatile("mbarrier.init.shared.b64 [%0], %1;"
                     :: "r"(smem_u32(&sBarSto)), "r"(8u) : "memory");
    __syncthreads();
    asm volatile("barrier.cluster.arrive.aligned;" ::: "memory");
    asm volatile("barrier.cluster.wait.aligned;" ::: "memory");

    // push mapping: threads tid>>6 -> dest rank; lane q0=tid&63 pushes
    // float4 slots q0 and q0+64 of the 128-float4 stage.
    const int pr = tid >> 6, q0 = tid & 63;
    unsigned pushBase;
    {
        unsigned l = smem_u32(&sH[(int)rank * 2 * SEG]);  // feats 64r..: kseg = 2*rank
        asm("mapa.shared::cluster.u32 %0, %1, %2;" : "=r"(pushBase) : "r"(l), "r"(pr));
    }
    const unsigned barL = smem_u32(&sBarSto);
    unsigned barR = 0;
    if (tid < 8)
        asm("mapa.shared::cluster.u32 %0, %1, %2;" : "=r"(barR) : "r"(barL), "r"(tid));

    // writer identity: lanes ks<8 -> (feature fs = ks&1, batch pair bp = ks>>1)
    const bool wr = (ks < 8);
    const int fs = ks & 1, bp = ks >> 1;
    const int wf = jbase + jq + (fs << 5);
    const int bA = gb0 + 2 * bp, bB = bA + 1;
    const int wslot = (jq + (fs << 5)) * 4 + bp;  // float2 slot in stage

    // NOTE: destination layout check — feature wf lands in peer's sH at
    // kseg = wf>>5 = 2*rank + (jq+(fs<<5))>>5, offset (wf&31)*8 + batch.
    // The staged [feat][batch] float2 block at sStage maps linearly onto
    // sH[2*rank*SEG ...] when SEG==256; with SEG=260 padding we must push
    // per-kseg halves: stage float4 q (feat fq=q>>1 local, pair of batches)
    // -> dest offset (q>=64 half selects kseg 2*rank+1).
    // Handled below by splitting the q index.

    float xvA = 0.f, xvB = 0.f;
    if (wr) {
        if (src) {
            int tA = src[(size_t)bA * SEQ + t0];
            int tB = src[(size_t)bB * SEQ + t0];
            xvA = __ldg(&xterm[(size_t)tA * HID + wf]);
            xvB = __ldg(&xterm[(size_t)tB * HID + wf]);
        } else {
            xvA = __ldg(&xterm[((size_t)t0 * BATCH + bA) * HID + wf]);
            xvB = __ldg(&xterm[((size_t)t0 * BATCH + bB) * HID + wf]);
        }
    }

    // push addresses: slot q covers feats [q>>1 local], i.e. local feat
    // lf = q/2 (two batch-float4 per feat: q even -> b0..b3, odd -> b4..b7).
    // dest float offset = (lf>=32 ? SEG : 0) + (lf&31)*8 + (q&1)*4  within
    // kseg base 2*rank. Precompute both slots' byte offsets.
    const int lfA = q0 >> 1, lfB = (q0 + 64) >> 1;
    const unsigned offA = (unsigned)(((lfA >> 5) * SEG + (lfA & 31) * 8 + (q0 & 1) * 4) * 4);
    const unsigned offB = (unsigned)(((lfB >> 5) * SEG + (lfB & 31) * 8 + (q0 & 1) * 4) * 4);

    unsigned phase = 0;
    const int tEnd = t0 + CHUNK;

    for (int t = t0; t < tEnd; ++t) {
        if (t > t0) { mbar_wait(barL, phase); phase ^= 1u; }

        const float* hb = sH + (t & 1) * HBUFV + ks * SEG;
        unsigned long long a01_0 = 0, a23_0 = 0, a45_0 = 0, a67_0 = 0;
        unsigned long long a01_1 = 0, a23_1 = 0, a45_1 = 0, a67_1 = 0;
#pragma unroll
        for (int i = 0; i < 32; ++i) {
            ulonglong2 hA = *(const ulonglong2*)(hb + i * 8);        // b0..b3
            ulonglong2 hB = *(const ulonglong2*)(hb + i * 8 + 4);    // b4..b7
            unsigned long long p0 = pack2(w0[i]);
            unsigned long long p1 = pack2(w1[i]);
            fma2(a01_0, p0, hA.x); fma2(a23_0, p0, hA.y);
            fma2(a45_0, p0, hB.x); fma2(a67_0, p0, hB.y);
            fma2(a01_1, p1, hA.x); fma2(a23_1, p1, hA.y);
            fma2(a45_1, p1, hB.x); fma2(a67_1, p1, hB.y);
        }
#pragma unroll
        for (int m = 1; m <= 8; m <<= 1) {
            a01_0 = add2(a01_0, __shfl_xor_sync(0xffffffffu, a01_0, m));
            a23_0 = add2(a23_0, __shfl_xor_sync(0xffffffffu, a23_0, m));
            a45_0 = add2(a45_0, __shfl_xor_sync(0xffffffffu, a45_0, m));
            a67_0 = add2(a67_0, __shfl_xor_sync(0xffffffffu, a67_0, m));
            a01_1 = add2(a01_1, __shfl_xor_sync(0xffffffffu, a01_1, m));
            a23_1 = add2(a23_1, __shfl_xor_sync(0xffffffffu, a23_1, m));
            a45_1 = add2(a45_1, __shfl_xor_sync(0xffffffffu, a45_1, m));
            a67_1 = add2(a67_1, __shfl_xor_sync(0xffffffffu, a67_1, m));
        }

        float hA = 0.f, hB = 0.f;
        if (wr) {
            unsigned long long s01 = fs ? a01_1 : a01_0;
            unsigned long long s23 = fs ? a23_1 : a23_0;
            unsigned long long s45 = fs ? a45_1 : a45_0;
            unsigned long long s67 = fs ? a67_1 : a67_0;
            unsigned long long ap = (bp == 0) ? s01 : (bp == 1) ? s23 : (bp == 2) ? s45 : s67;
            hA = tanhf(lo2(ap) + xvA);
            hB = tanhf(hi2(ap) + xvB);
            ((float2*)sStage)[wslot] = make_float2(hA, hB);
        }
        __syncthreads();

        const bool last = (t == tEnd - 1);
        if (!last) {
            const unsigned bo = (unsigned)(((t + 1) & 1)) * HBUF_BYTES;
            float4 v0 = sStage[q0];
            float4 v1 = sStage[q0 + 64];
            asm volatile("st.shared::cluster.v4.f32 [%0], {%1, %2, %3, %4};"
                         :: "r"(pushBase + bo + offA),
                            "f"(v0.x), "f"(v0.y), "f"(v0.z), "f"(v0.w) : "memory");
            asm volatile("st.shared::cluster.v4.f32 [%0], {%1, %2, %3, %4};"
                         :: "r"(pushBase + bo + offB),
                            "f"(v1.x), "f"(v1.y), "f"(v1.z), "f"(v1.w) : "memory");
            __syncthreads();
            if (tid < 8)
                asm volatile("mbarrier.arrive.release.cluster.shared::cluster.b64 _, [%0];"
                             :: "r"(barR) : "memory");
        }

        // off critical path: global stores + next-x prefetch (writer lanes)
        if (wr) {
            if (ys) {
                ys[((size_t)t * BATCH + bA) * HID + wf] = hA;
                ys[((size_t)t * BATCH + bB) * HID + wf] = hB;
            }
            if (last && hOut) {
                hOut[(size_t)bA * HID + wf] = hA;
                hOut[(size_t)bB * HID + wf] = hB;
            }
            if (t == SEQ - 1 && outh) {
                outh[(size_t)bA * HID + wf] = hA;
                outh[(size_t)bB * HID + wf] = hB;
            }
            int tn = (t + 1 < tEnd) ? (t + 1) : (tEnd - 1);
            if (src) {
                int tA = src[(size_t)bA * SEQ + tn];
                int tB = src[(size_t)bB * SEQ + tn];
                xvA = __ldg(&xterm[(size_t)tA * HID + wf]);
                xvB = __ldg(&xterm[(size_t)tB * HID + wf]);
            } else {
                xvA = __ldg(&xterm[((size_t)tn * BATCH + bA) * HID + wf]);
                xvB = __ldg(&xterm[((size_t)tn * BATCH + bB) * HID + wf]);
            }
        }
    }

    asm volatile("barrier.cluster.arrive.aligned;" ::: "memory");
    asm volatile("barrier.cluster.wait.aligned;" ::: "memory");
}

// ---------------- launch ----------------
extern "C" void kernel_launch(void* const* d_in, const int* in_sizes, int n_in,
                              void* d_out, int out_size)
{
    const int* src = (const int*)d_in[0];
    const float* embed = (const float*)d_in[1];
    const float* W_ih = (const float*)d_in[2];   // [2][512][512]
    const float* W_hh = (const float*)d_in[3];   // [2][512][512]
    const float* b_ih = (const float*)d_in[4];   // [2][512]
    const float* b_hh = (const float*)d_in[5];   // [2][512]
    float* out = (float*)d_out;                  // [2][64][512]

    float *pE, *pYs, *pXb, *pH1;
    cudaGetSymbolAddress((void**)&pE, g_E);
    cudaGetSymbolAddress((void**)&pYs, g_ys);
    cudaGetSymbolAddress((void**)&pXb, g_xb);
    cudaGetSymbolAddress((void**)&pH1, g_h1);

    static bool s_init = false;
    static cudaStream_t sB;
    static cudaEvent_t evPipe[NCHUNK], evJoin;
    if (!s_init) {
        cudaStreamCreateWithFlags(&sB, cudaStreamNonBlocking);
        for (int i = 0; i < NCHUNK; ++i)
            cudaEventCreateWithFlags(&evPipe[i], cudaEventDisableTiming);
        cudaEventCreateWithFlags(&evJoin, cudaEventDisableTiming);
        s_init = true;
    }

    gemm_bias_kernel<<<dim3(VOCAB / BM, HID / BN), 256>>>(embed, W_ih, b_ih, b_hh, pE);

    const float* Wih1 = W_ih + (size_t)HID * HID;
    const float* Whh0 = W_hh;
    const float* Whh1 = W_hh + (size_t)HID * HID;

    for (int c = 0; c < NCHUNK; ++c) {
        int t0 = c * CHUNK;
        rnn_chunk_kernel<<<64, 512>>>(
            pE, src, Whh0, pYs, out,
            (c == 0) ? nullptr : pYs + ((size_t)t0 - 1) * BATCH * HID,
            nullptr, t0);
        cudaEventRecord(evPipe[c], 0);

        cudaStreamWaitEvent(sB, evPipe[c], 0);
        gemm_bias_kernel<<<dim3(CHUNK * BATCH / BM, HID / BN), 256, 0, sB>>>(
            pYs + (size_t)t0 * BATCH * HID, Wih1, b_ih + HID, b_hh + HID,
            pXb + (size_t)t0 * BATCH * HID);
        rnn_chunk_kernel<<<64, 512, 0, sB>>>(
            pXb, nullptr, Whh1, nullptr, out + (size_t)BATCH * HID,
            (c == 0) ? nullptr : pH1, pH1, t0);
    }
    cudaEventRecord(evJoin, sB);
    cudaStreamWaitEvent(0, evJoin, 0);
}